// round 4
// baseline (speedup 1.0000x reference)
#include <cuda_runtime.h>
#include <math.h>

// SpatialGRU 32x32 wavefront, B=64, U=64, C=64.
// R4: diagonal-parallel persistent kernel, 148 CTAs (1 per SM), per-cell flag
// sync, Z computed in place into the precomputed x@W+bias buffer.

#define TPB 256
#define G   148

__device__ float g_x[1024 * 4096];       // x[t][b][c]
__device__ float g_XZ[1024 * 28672];     // x@W+bias -> overwritten with Z[t]
__device__ float g_xWij[1024 * 4096];    // x@W_ij + b_ij
__device__ float g_S[1024 * 4096];       // h state per cell
__device__ int   g_zdone[1024];          // counts to 7
__device__ int   g_hdone[1024];          // counts to 2

// ---------------------------------------------------------------------------
__global__ void k_init() {
    int idx = blockIdx.x * blockDim.x + threadIdx.x;
    if (idx < 1024) { g_zdone[idx] = 0; g_hdone[idx] = 0; }
}

// ---------------------------------------------------------------------------
// transpose inputs (B,C,32,32) -> g_x[t][b][c]
__global__ void k_transpose(const float* __restrict__ in) {
    __shared__ float tile[32][33];
    int b = blockIdx.z;
    int t0 = blockIdx.x * 32;
    int c0 = blockIdx.y * 32;
    int tx = threadIdx.x, ty = threadIdx.y;
    tile[ty][tx] = in[b * 65536 + (c0 + ty) * 1024 + t0 + tx];
    __syncthreads();
    g_x[(t0 + ty) * 4096 + b * 64 + c0 + tx] = tile[tx][ty];
}

// ---------------------------------------------------------------------------
// Precompute: XZ[t] = x[t]@W[192:256,:] + bias[:448];  xWij[t] = x[t]@W_ij + b_ij
// grid (1024, 8), block 256. ct 0..6 -> 64-col slices of XZ; ct==7 -> xWij.
__global__ void k_pre(const float* __restrict__ W, const float* __restrict__ Wij,
                      const float* __restrict__ bias) {
    __shared__ float sXT[64 * 65];
    __shared__ float sB[64 * 64];
    int t = blockIdx.x, ct = blockIdx.y, tid = threadIdx.x;
    for (int idx = tid; idx < 4096; idx += TPB) {
        int rr = idx >> 6, k = idx & 63;
        sXT[k * 65 + rr] = g_x[t * 4096 + idx];
        sB[idx] = (ct < 7) ? W[(192 + rr) * 448 + ct * 64 + k] : Wij[rr * 64 + k];
    }
    __syncthreads();
    int r = tid & 63;
    int cb = (tid >> 6) << 4;
    const float* bsrc = (ct < 7) ? (bias + ct * 64 + cb) : (bias + 448 + cb);
    float acc[16];
#pragma unroll
    for (int s = 0; s < 16; ++s) acc[s] = bsrc[s];
#pragma unroll 4
    for (int k = 0; k < 64; ++k) {
        float a = sXT[k * 65 + r];
        const float4* bp = (const float4*)&sB[k * 64 + cb];
        float4 b0 = bp[0], b1 = bp[1], b2 = bp[2], b3 = bp[3];
        acc[0]  += a * b0.x; acc[1]  += a * b0.y; acc[2]  += a * b0.z; acc[3]  += a * b0.w;
        acc[4]  += a * b1.x; acc[5]  += a * b1.y; acc[6]  += a * b1.z; acc[7]  += a * b1.w;
        acc[8]  += a * b2.x; acc[9]  += a * b2.y; acc[10] += a * b2.z; acc[11] += a * b2.w;
        acc[12] += a * b3.x; acc[13] += a * b3.y; acc[14] += a * b3.z; acc[15] += a * b3.w;
    }
    float* o = (ct < 7) ? &g_XZ[t * 28672 + r * 448 + ct * 64 + cb]
                        : &g_xWij[t * 4096 + r * 64 + cb];
#pragma unroll
    for (int s = 0; s < 16; ++s) o[s] = acc[s];
}

// ---------------------------------------------------------------------------
// Persistent diagonal-parallel scan. grid 148, block 256, 1 CTA/SM.
// p1 unit: (cell, 64-col slice) -> Z slice in place into g_XZ, bump zdone.
// p2 unit: (cell, 32-col half)  -> G=r*hcat, @U_rec, gates, h, bump hdone.
extern "C" __global__ void __launch_bounds__(TPB, 1)
k_scan(const float* __restrict__ W, const float* __restrict__ Urec,
       float* __restrict__ out) {
    extern __shared__ float sm[];
    float* sB  = sm;             // p1: W slice [192][64] ; p2: U slice [192][32]
    float* sAT = sm + 12288;     // [192][65] hcat^T (p1) / G^T (p2)

    int g = blockIdx.x;
    int tid = threadIdx.x;
    int r = tid & 63;
    int cb = (tid >> 6) << 4;     // p1: 16-col group
    int n0 = (tid >> 6) << 3;     // p2: 8-col group

    for (int d = 0; d < 63; ++d) {
        int i0 = d > 31 ? d - 31 : 0;
        int i1 = d < 31 ? d : 31;
        int nc = i1 - i0 + 1;

        // ================= phase 1 =================
        int n1 = nc * 7;
        for (int u = g; u < n1; u += G) {
            int c = u % nc, s = u / nc;
            int i = i0 + c, j = d - i, t = i * 32 + j;

            if (tid == 0) {
                if (i > 0)          while (((volatile int*)g_hdone)[t - 32] < 2) {}
                if (j > 0)          while (((volatile int*)g_hdone)[t - 1]  < 2) {}
                if (i > 0 && j > 0) while (((volatile int*)g_hdone)[t - 33] < 2) {}
            }
            __syncthreads();

            const float* srcT = (i > 0)          ? &g_S[(t - 32) * 4096] : (const float*)0;
            const float* srcL = (j > 0)          ? &g_S[(t - 1)  * 4096] : (const float*)0;
            const float* srcD = (i > 0 && j > 0) ? &g_S[(t - 33) * 4096] : (const float*)0;

            for (int idx = tid; idx < 12288; idx += TPB) {
                int k = idx >> 6, n = idx & 63;
                sB[idx] = W[k * 448 + s * 64 + n];
            }
            for (int idx = tid; idx < 4096; idx += TPB) {
                int rr = idx >> 6, c2 = idx & 63;
                sAT[c2 * 65 + rr]         = srcT ? __ldcg(&srcT[idx]) : 0.f;
                sAT[(64 + c2) * 65 + rr]  = srcL ? __ldcg(&srcL[idx]) : 0.f;
                sAT[(128 + c2) * 65 + rr] = srcD ? __ldcg(&srcD[idx]) : 0.f;
            }
            __syncthreads();

            float* xz = &g_XZ[t * 28672 + r * 448 + s * 64 + cb];
            float acc[16];
#pragma unroll
            for (int q = 0; q < 16; ++q) acc[q] = __ldcg(&xz[q]);
#pragma unroll 4
            for (int k = 0; k < 192; ++k) {
                float a = sAT[k * 65 + r];
                const float4* bp = (const float4*)&sB[k * 64 + cb];
                float4 b0 = bp[0], b1 = bp[1], b2 = bp[2], b3 = bp[3];
                acc[0]  += a * b0.x; acc[1]  += a * b0.y; acc[2]  += a * b0.z; acc[3]  += a * b0.w;
                acc[4]  += a * b1.x; acc[5]  += a * b1.y; acc[6]  += a * b1.z; acc[7]  += a * b1.w;
                acc[8]  += a * b2.x; acc[9]  += a * b2.y; acc[10] += a * b2.z; acc[11] += a * b2.w;
                acc[12] += a * b3.x; acc[13] += a * b3.y; acc[14] += a * b3.z; acc[15] += a * b3.w;
            }
#pragma unroll
            for (int q = 0; q < 16; ++q) xz[q] = acc[q];
            __threadfence();
            __syncthreads();
            if (tid == 0) atomicAdd(&g_zdone[t], 1);
        }

        // ================= phase 2 =================
        int n2 = nc * 2;
        for (int u = g; u < n2; u += G) {
            int c = u % nc, half = u / nc;
            int i = i0 + c, j = d - i, t = i * 32 + j;

            if (tid == 0) while (((volatile int*)g_zdone)[t] < 7) {}
            __syncthreads();

            const float* srcT = (i > 0)          ? &g_S[(t - 32) * 4096] : (const float*)0;
            const float* srcL = (j > 0)          ? &g_S[(t - 1)  * 4096] : (const float*)0;
            const float* srcD = (i > 0 && j > 0) ? &g_S[(t - 33) * 4096] : (const float*)0;
            const float* Z = &g_XZ[t * 28672];

            // G^T[c2][rr] = sigmoid(Z[rr][c2]) * concat[hL|hT|hD][rr][c2&63]
            for (int idx = tid; idx < 12288; idx += TPB) {
                int rr = idx / 192;
                int c2 = idx - rr * 192;
                float z = __ldcg(&Z[rr * 448 + c2]);
                float sg = 1.f / (1.f + __expf(-z));
                const float* hs = (c2 < 64) ? srcL : ((c2 < 128) ? srcT : srcD);
                float hv = hs ? __ldcg(&hs[rr * 64 + (c2 & 63)]) : 0.f;
                sAT[c2 * 65 + rr] = sg * hv;
            }
            for (int idx = tid; idx < 6144; idx += TPB) {
                int k = idx >> 5, n = idx & 31;
                sB[idx] = Urec[k * 64 + half * 32 + n];
            }
            __syncthreads();

            float p[8];
#pragma unroll
            for (int q = 0; q < 8; ++q) p[q] = 0.f;
#pragma unroll 4
            for (int k = 0; k < 192; ++k) {
                float a = sAT[k * 65 + r];
                const float4* up = (const float4*)&sB[k * 32 + n0];
                float4 u0 = up[0], u1 = up[1];
                p[0] += a * u0.x; p[1] += a * u0.y; p[2] += a * u0.z; p[3] += a * u0.w;
                p[4] += a * u1.x; p[5] += a * u1.y; p[6] += a * u1.z; p[7] += a * u1.w;
            }

#pragma unroll
            for (int q = 0; q < 8; ++q) {
                int n = half * 32 + n0 + q;
                float zi = __ldcg(&Z[r * 448 + 192 + n]);
                float zl = __ldcg(&Z[r * 448 + 256 + n]);
                float zt = __ldcg(&Z[r * 448 + 320 + n]);
                float zd = __ldcg(&Z[r * 448 + 384 + n]);
                float m = fmaxf(fmaxf(zi, zl), fmaxf(zt, zd));
                float ei = __expf(zi - m), el = __expf(zl - m);
                float et = __expf(zt - m), ed = __expf(zd - m);
                float inv = 1.f / (ei + el + et + ed);
                float hl = srcL ? __ldcg(&srcL[r * 64 + n]) : 0.f;
                float ht = srcT ? __ldcg(&srcT[r * 64 + n]) : 0.f;
                float hd = srcD ? __ldcg(&srcD[r * 64 + n]) : 0.f;
                float pre = __ldcg(&g_xWij[t * 4096 + r * 64 + n]) + p[q];
                pre = fminf(fmaxf(pre, -15.f), 15.f);
                float e2 = __expf(2.f * pre);
                float hh = (e2 - 1.f) / (e2 + 1.f);
                float h = (el * hl + et * ht + ed * hd + ei * hh) * inv;
                g_S[t * 4096 + r * 64 + n] = h;
                if (t == 1023) out[r * 64 + n] = h;
            }
            __threadfence();
            __syncthreads();
            if (tid == 0) atomicAdd(&g_hdone[t], 1);
        }
    }
}

// ---------------------------------------------------------------------------
extern "C" void kernel_launch(void* const* d_in, const int* in_sizes, int n_in,
                              void* d_out, int out_size) {
    const float* in   = (const float*)d_in[0];  // (64,64,32,32)
    const float* W    = (const float*)d_in[1];  // (256,448)
    const float* Urec = (const float*)d_in[2];  // (192,64)
    const float* bias = (const float*)d_in[3];  // (512)
    const float* Wij  = (const float*)d_in[4];  // (64,64)
    float* out = (float*)d_out;                 // (64,64)

    static int smem_set = 0;
    if (!smem_set) {
        // 99072 B used; request 116736 to force 1 CTA/SM (no straggler SMs,
        // grid 148 <= SM count so all CTAs resident -> no spin deadlock).
        cudaFuncSetAttribute(k_scan, cudaFuncAttributeMaxDynamicSharedMemorySize,
                             116736);
        smem_set = 1;
    }

    k_init<<<4, 256>>>();
    k_transpose<<<dim3(32, 2, 64), dim3(32, 32)>>>(in);
    k_pre<<<dim3(1024, 8), TPB>>>(W, Wij, bias);
    k_scan<<<G, TPB, 116736>>>(W, Urec, out);
}